// round 6
// baseline (speedup 1.0000x reference)
#include <cuda_runtime.h>
#include <cuda_bf16.h>
#include <cstdint>

constexpr int NN = 100000;    // nodes
constexpr int NE = 3200000;   // edges
constexpr int CIN = 512;
constexpr int CH  = 40;
constexpr int COUT = 20;

// Scratch (__device__ globals: allocation-free per harness rules)
__device__ __align__(16) float g_h1[(size_t)NN * CH];
__device__ __align__(16) float g_acc1[(size_t)NN * CH];
__device__ __align__(16) float g_h2[(size_t)NN * COUT];
__device__ float g_dinv[NN];
__device__ int   g_deg[NN];       // in-degree WITHOUT self loop
__device__ int   g_rowstart[NN];
__device__ int   g_cursor[NN];
__device__ int   g_csr[NE];       // src ids grouped by dst

// ---------------------------------------------------------------------------
// helpers
// ---------------------------------------------------------------------------
__device__ __forceinline__ unsigned long long ffma2(unsigned long long a,
                                                    unsigned long long b,
                                                    unsigned long long c) {
    unsigned long long d;
    asm("fma.rn.f32x2 %0, %1, %2, %3;" : "=l"(d) : "l"(a), "l"(b), "l"(c));
    return d;
}

__device__ __forceinline__ void cp_async16(uint32_t dst_smem, const void* src,
                                           int src_bytes) {
    asm volatile("cp.async.cg.shared.global [%0], [%1], 16, %2;"
                 :: "r"(dst_smem), "l"(src), "r"(src_bytes));
}
__device__ __forceinline__ void cp_commit() {
    asm volatile("cp.async.commit_group;");
}
template <int N>
__device__ __forceinline__ void cp_wait() {
    asm volatile("cp.async.wait_group %0;" :: "n"(N));
}

__device__ __forceinline__ uint32_t smem_u32(const void* p) {
    uint32_t a;
    asm("{ .reg .u64 t; cvta.to.shared.u64 t, %1; cvt.u32.u64 %0, t; }"
        : "=r"(a) : "l"(p));
    return a;
}

// ---------------------------------------------------------------------------
// degree / dinv / CSR build
// ---------------------------------------------------------------------------
__global__ void k_deg_init() {
    int i = blockIdx.x * 256 + threadIdx.x;
    if (i < NN) g_deg[i] = 0;
}
__global__ void k_deg_count(const int* __restrict__ ei) {
    int e = blockIdx.x * 256 + threadIdx.x;
    if (e < NE) atomicAdd(&g_deg[ei[NE + e]], 1);
}
__global__ void k_dinv() {
    int i = blockIdx.x * 256 + threadIdx.x;
    if (i < NN) g_dinv[i] = rsqrtf((float)(g_deg[i] + 1));  // +1 self loop
}

// single-block exclusive prefix scan of g_deg -> g_rowstart / g_cursor
__global__ __launch_bounds__(1024) void k_scan() {
    __shared__ int ssum[1024];
    const int t = threadIdx.x;
    const int CHK = (NN + 1023) / 1024;  // 98
    int beg = t * CHK;
    int end = min(beg + CHK, NN);
    int s = 0;
    for (int i = beg; i < end; i++) s += g_deg[i];
    ssum[t] = s;
    __syncthreads();
    // Hillis-Steele inclusive scan over 1024 partials
    for (int off = 1; off < 1024; off <<= 1) {
        int v = (t >= off) ? ssum[t - off] : 0;
        __syncthreads();
        ssum[t] += v;
        __syncthreads();
    }
    int run = ssum[t] - s;  // exclusive prefix for this chunk
    for (int i = beg; i < end; i++) {
        g_rowstart[i] = run;
        g_cursor[i] = run;
        run += g_deg[i];
    }
}

__global__ void k_fill(const int* __restrict__ ei) {
    int e = blockIdx.x * 256 + threadIdx.x;
    if (e < NE) {
        int s = ei[e];
        int d = ei[NE + e];
        int p = atomicAdd(&g_cursor[d], 1);
        g_csr[p] = s;
    }
}

// ---------------------------------------------------------------------------
// GEMM1: hs1 = dinv * (x @ W1).  M=100000, K=512, N=40.  (round-2 config,
// measured 107us). 64 threads/block, 128 rows. Thread: 8 rows x 10 cols.
// ---------------------------------------------------------------------------
constexpr int KT = 16;               // k per tile
constexpr int NT = CIN / KT;         // 32 tiles
constexpr int RT = 128;              // rows per block
constexpr int XROW = 32;             // padded floats per row in xs

__global__ __launch_bounds__(64) void k_gemm1(const float* __restrict__ x,
                                              const float* __restrict__ W1) {
    __shared__ __align__(16) float xs[2][RT * XROW];   // 2 x 16 KB
    __shared__ __align__(16) float ws[2][KT * CH];     // 2 x 2.5 KB

    const int tid = threadIdx.x;
    const int rp = tid >> 2;          // 0..15 : rows rp*8 .. rp*8+7
    const int ct = tid & 3;           // 0..3  : cols ct*10 .. ct*10+9
    const int row0 = blockIdx.x * RT;

    const uint32_t xs_b[2] = { smem_u32(&xs[0][0]), smem_u32(&xs[1][0]) };
    const uint32_t ws_b[2] = { smem_u32(&ws[0][0]), smem_u32(&ws[1][0]) };

    auto stage = [&](int t) {
        int kt = t * KT;
        int buf = t & 1;
#pragma unroll
        for (int i = 0; i < 8; i++) {
            int idx = tid + 64 * i;         // 0..511
            int r = idx >> 2;
            int q = idx & 3;
            int gr = row0 + r;
            const float* src = x + (size_t)gr * CIN + kt + q * 4;
            uint32_t dst = xs_b[buf] + (uint32_t)(r * XROW + 4 * ((q + (r >> 3)) & 7)) * 4u;
            cp_async16(dst, src, (gr < NN) ? 16 : 0);
        }
#pragma unroll
        for (int i = 0; i < 3; i++) {
            int idx = tid + 64 * i;
            if (idx < 160)
                cp_async16(ws_b[buf] + (uint32_t)idx * 16u, W1 + kt * CH + idx * 4, 16);
        }
    };

    unsigned long long acc[8][5];
#pragma unroll
    for (int r = 0; r < 8; r++)
#pragma unroll
        for (int j = 0; j < 5; j++) acc[r][j] = 0ull;

    stage(0);
    cp_commit();

    for (int t = 0; t < NT; t++) {
        int buf = t & 1;
        if (t + 1 < NT) {
            stage(t + 1);
            cp_commit();
            cp_wait<1>();
        } else {
            cp_wait<0>();
        }
        __syncthreads();

        const float* xsb = &xs[buf][0];
        const float* wsb = &ws[buf][0];
#pragma unroll
        for (int k = 0; k < KT; k++) {
            unsigned long long wv[5];
            const float* wk = wsb + k * CH + ct * 10;
#pragma unroll
            for (int j = 0; j < 5; j++)
                wv[j] = *(const unsigned long long*)(wk + 2 * j);
            int pos = 4 * (((k >> 2) + rp) & 7) + (k & 3);
#pragma unroll
            for (int r = 0; r < 8; r++) {
                float xv = xsb[(rp * 8 + r) * XROW + pos];
                unsigned long long xd;
                asm("mov.b64 %0, {%1, %1};" : "=l"(xd) : "f"(xv));
#pragma unroll
                for (int j = 0; j < 5; j++)
                    acc[r][j] = ffma2(xd, wv[j], acc[r][j]);
            }
        }
        __syncthreads();
    }

    // epilogue: scale by dinv, write message buffer only (pull agg inits from it)
#pragma unroll
    for (int r = 0; r < 8; r++) {
        int gr = row0 + rp * 8 + r;
        if (gr < NN) {
            float dv = g_dinv[gr];
#pragma unroll
            for (int j = 0; j < 5; j++) {
                unsigned long long a = acc[r][j];
                float lo = __uint_as_float((unsigned)a) * dv;
                float hi = __uint_as_float((unsigned)(a >> 32)) * dv;
                int c = ct * 10 + 2 * j;
                *(float2*)&g_h1[(size_t)gr * CH + c] = make_float2(lo, hi);
            }
        }
    }
}

// ---------------------------------------------------------------------------
// Aggregation layer 1 (PULL): 10 threads per node, each owns one float4
// slice of the 40 channels. acc init = own hs (self loop), then gather
// neighbors via CSR. Single write to g_acc1.
// ---------------------------------------------------------------------------
__global__ void k_agg1() {
    unsigned t = blockIdx.x * 256u + threadIdx.x;
    unsigned node = t / 10u;
    if (node >= (unsigned)NN) return;
    unsigned q = t - node * 10u;
    const float4* base = (const float4*)g_h1;

    float4 acc = base[(size_t)node * 10 + q];   // self term (hs[node])
    int beg = g_rowstart[node];
    int len = g_deg[node];

    int i = 0;
    for (; i + 2 <= len; i += 2) {
        int s0 = __ldg(&g_csr[beg + i]);
        int s1 = __ldg(&g_csr[beg + i + 1]);
        float4 v0 = base[(size_t)s0 * 10 + q];
        float4 v1 = base[(size_t)s1 * 10 + q];
        acc.x += v0.x + v1.x;
        acc.y += v0.y + v1.y;
        acc.z += v0.z + v1.z;
        acc.w += v0.w + v1.w;
    }
    if (i < len) {
        int s0 = __ldg(&g_csr[beg + i]);
        float4 v0 = base[(size_t)s0 * 10 + q];
        acc.x += v0.x; acc.y += v0.y; acc.z += v0.z; acc.w += v0.w;
    }
    ((float4*)g_acc1)[(size_t)node * 10 + q] = acc;
}

// ---------------------------------------------------------------------------
// Layer-1 finish + GEMM2: r = relu(dinv*acc1 + b1); hs2 = dinv * (r @ W2)
// ---------------------------------------------------------------------------
__global__ __launch_bounds__(128) void k_layer2(const float* __restrict__ W2,
                                                const float* __restrict__ b1) {
    __shared__ float w2s[CH * COUT];
    __shared__ float b1s[CH];
    int tid = threadIdx.x;
    for (int i = tid; i < CH * COUT; i += 128) w2s[i] = W2[i];
    if (tid < CH) b1s[tid] = b1[tid];
    __syncthreads();

    int r = blockIdx.x * 128 + tid;
    if (r >= NN) return;
    float dv = g_dinv[r];

    float rv[CH];
#pragma unroll
    for (int q = 0; q < 10; q++) {
        float4 v = *(const float4*)&g_acc1[(size_t)r * CH + q * 4];
        rv[4 * q + 0] = fmaxf(dv * v.x + b1s[4 * q + 0], 0.f);
        rv[4 * q + 1] = fmaxf(dv * v.y + b1s[4 * q + 1], 0.f);
        rv[4 * q + 2] = fmaxf(dv * v.z + b1s[4 * q + 2], 0.f);
        rv[4 * q + 3] = fmaxf(dv * v.w + b1s[4 * q + 3], 0.f);
    }

    float acc[COUT];
#pragma unroll
    for (int c = 0; c < COUT; c++) acc[c] = 0.f;
#pragma unroll
    for (int k = 0; k < CH; k++) {
        float xv = rv[k];
#pragma unroll
        for (int c = 0; c < COUT; c++)
            acc[c] = fmaf(xv, w2s[k * COUT + c], acc[c]);
    }

#pragma unroll
    for (int q = 0; q < 5; q++) {
        float4 o = make_float4(dv * acc[4 * q + 0], dv * acc[4 * q + 1],
                               dv * acc[4 * q + 2], dv * acc[4 * q + 3]);
        *(float4*)&g_h2[(size_t)r * COUT + 4 * q] = o;
    }
}

// ---------------------------------------------------------------------------
// Aggregation layer 2 (PULL) fused with final epilogue:
// 5 threads per node. out = dinv * (self + sum neighbors) + b2
// ---------------------------------------------------------------------------
__global__ void k_agg2(float* __restrict__ out, const float* __restrict__ b2) {
    unsigned t = blockIdx.x * 256u + threadIdx.x;
    unsigned node = t / 5u;
    if (node >= (unsigned)NN) return;
    unsigned q = t - node * 5u;
    const float4* base = (const float4*)g_h2;

    float4 acc = base[(size_t)node * 5 + q];    // self term
    int beg = g_rowstart[node];
    int len = g_deg[node];

    int i = 0;
    for (; i + 2 <= len; i += 2) {
        int s0 = __ldg(&g_csr[beg + i]);
        int s1 = __ldg(&g_csr[beg + i + 1]);
        float4 v0 = base[(size_t)s0 * 5 + q];
        float4 v1 = base[(size_t)s1 * 5 + q];
        acc.x += v0.x + v1.x;
        acc.y += v0.y + v1.y;
        acc.z += v0.z + v1.z;
        acc.w += v0.w + v1.w;
    }
    if (i < len) {
        int s0 = __ldg(&g_csr[beg + i]);
        float4 v0 = base[(size_t)s0 * 5 + q];
        acc.x += v0.x; acc.y += v0.y; acc.z += v0.z; acc.w += v0.w;
    }

    float dv = g_dinv[node];
    float4 b = *(const float4*)&b2[q * 4];
    float4 o = make_float4(dv * acc.x + b.x, dv * acc.y + b.y,
                           dv * acc.z + b.z, dv * acc.w + b.w);
    ((float4*)out)[(size_t)node * 5 + q] = o;
}

// ---------------------------------------------------------------------------
extern "C" void kernel_launch(void* const* d_in, const int* in_sizes, int n_in,
                              void* d_out, int out_size) {
    const float* x  = (const float*)d_in[0];
    const int*   ei = (const int*)d_in[1];
    const float* W1 = (const float*)d_in[2];
    const float* b1 = (const float*)d_in[3];
    const float* W2 = (const float*)d_in[4];
    const float* b2 = (const float*)d_in[5];
    float* out = (float*)d_out;

    k_deg_init<<<(NN + 255) / 256, 256>>>();
    k_deg_count<<<(NE + 255) / 256, 256>>>(ei);
    k_dinv<<<(NN + 255) / 256, 256>>>();
    k_scan<<<1, 1024>>>();
    k_fill<<<(NE + 255) / 256, 256>>>(ei);
    k_gemm1<<<(NN + RT - 1) / RT, 64>>>(x, W1);
    {
        long long th = (long long)NN * 10;
        k_agg1<<<(unsigned)((th + 255) / 256), 256>>>();
    }
    k_layer2<<<(NN + 127) / 128, 128>>>(W2, b1);
    {
        long long th = (long long)NN * 5;
        k_agg2<<<(unsigned)((th + 255) / 256), 256>>>(out, b2);
    }
}

// round 11
// speedup vs baseline: 1.5449x; 1.5449x over previous
#include <cuda_runtime.h>
#include <cuda_bf16.h>
#include <cstdint>

constexpr int NN = 100000;    // nodes
constexpr int NE = 3200000;   // edges
constexpr int CIN = 512;
constexpr int CH  = 40;
constexpr int COUT = 20;

constexpr int SCAN_B  = 1024;
constexpr int SCAN_NB = (NN + SCAN_B - 1) / SCAN_B;   // 98

// Scratch (__device__ globals: allocation-free per harness rules)
__device__ __align__(16) float g_h1[(size_t)NN * CH];
__device__ __align__(16) float g_acc1[(size_t)NN * CH];
__device__ __align__(16) float g_h2[(size_t)NN * COUT];
__device__ float g_dinv[NN];
__device__ int   g_deg[NN];       // in-degree WITHOUT self loop
__device__ int   g_rowstart[NN];
__device__ int   g_cursor[NN];
__device__ int   g_csr[NE];       // src ids grouped by dst
__device__ int   g_scan[NN];      // in-block inclusive scan of deg
__device__ int   g_bsum[SCAN_NB]; // per-block totals -> exclusive offsets

// ---------------------------------------------------------------------------
// helpers
// ---------------------------------------------------------------------------
__device__ __forceinline__ unsigned long long ffma2(unsigned long long a,
                                                    unsigned long long b,
                                                    unsigned long long c) {
    unsigned long long d;
    asm("fma.rn.f32x2 %0, %1, %2, %3;" : "=l"(d) : "l"(a), "l"(b), "l"(c));
    return d;
}

__device__ __forceinline__ void cp_async16(uint32_t dst_smem, const void* src,
                                           int src_bytes) {
    asm volatile("cp.async.cg.shared.global [%0], [%1], 16, %2;"
                 :: "r"(dst_smem), "l"(src), "r"(src_bytes));
}
__device__ __forceinline__ void cp_commit() {
    asm volatile("cp.async.commit_group;");
}
template <int N>
__device__ __forceinline__ void cp_wait() {
    asm volatile("cp.async.wait_group %0;" :: "n"(N));
}

__device__ __forceinline__ uint32_t smem_u32(const void* p) {
    uint32_t a;
    asm("{ .reg .u64 t; cvta.to.shared.u64 t, %1; cvt.u32.u64 %0, t; }"
        : "=r"(a) : "l"(p));
    return a;
}

// ---------------------------------------------------------------------------
// degree / dinv / CSR build
// ---------------------------------------------------------------------------
__global__ void k_deg_init() {
    int i = blockIdx.x * 256 + threadIdx.x;
    if (i < NN) g_deg[i] = 0;
}
__global__ void k_deg_count(const int* __restrict__ ei) {
    int e = blockIdx.x * 256 + threadIdx.x;
    if (e < NE) atomicAdd(&g_deg[ei[NE + e]], 1);
}
__global__ void k_dinv() {
    int i = blockIdx.x * 256 + threadIdx.x;
    if (i < NN) g_dinv[i] = rsqrtf((float)(g_deg[i] + 1));  // +1 self loop
}

// --- parallel scan, phase 1: per-block inclusive scan + block totals -------
__global__ __launch_bounds__(SCAN_B) void k_scan1() {
    const int t = threadIdx.x, b = blockIdx.x;
    const int i = b * SCAN_B + t;
    int v = (i < NN) ? g_deg[i] : 0;
    const int lane = t & 31, warp = t >> 5;
    int s = v;
#pragma unroll
    for (int o = 1; o < 32; o <<= 1) {
        int u = __shfl_up_sync(~0u, s, o);
        if (lane >= o) s += u;
    }
    __shared__ int wsum[32];
    if (lane == 31) wsum[warp] = s;
    __syncthreads();
    if (warp == 0) {
        int ws = wsum[lane];
#pragma unroll
        for (int o = 1; o < 32; o <<= 1) {
            int u = __shfl_up_sync(~0u, ws, o);
            if (lane >= o) ws += u;
        }
        wsum[lane] = ws;
    }
    __syncthreads();
    int incl = s + (warp ? wsum[warp - 1] : 0);
    if (i < NN) g_scan[i] = incl;
    if (t == SCAN_B - 1) g_bsum[b] = incl;
}

// --- phase 2: exclusive scan of the 98 block totals (one small block) ------
__global__ __launch_bounds__(128) void k_scan2() {
    const int t = threadIdx.x;
    int v = (t < SCAN_NB) ? g_bsum[t] : 0;
    const int lane = t & 31, warp = t >> 5;
    int s = v;
#pragma unroll
    for (int o = 1; o < 32; o <<= 1) {
        int u = __shfl_up_sync(~0u, s, o);
        if (lane >= o) s += u;
    }
    __shared__ int wsum[4];
    if (lane == 31) wsum[warp] = s;
    __syncthreads();
    int add = 0;
    for (int w = 0; w < warp; w++) add += wsum[w];
    int incl = s + add;
    if (t < SCAN_NB) g_bsum[t] = incl - v;   // exclusive block offset
}

// --- phase 3: rowstart / cursor ---------------------------------------------
__global__ __launch_bounds__(SCAN_B) void k_scan3() {
    const int t = threadIdx.x, b = blockIdx.x;
    const int i = b * SCAN_B + t;
    if (i < NN) {
        int rs = g_bsum[b] + g_scan[i] - g_deg[i];
        g_rowstart[i] = rs;
        g_cursor[i] = rs;
    }
}

__global__ void k_fill(const int* __restrict__ ei) {
    int e = blockIdx.x * 256 + threadIdx.x;
    if (e < NE) {
        int s = ei[e];
        int d = ei[NE + e];
        int p = atomicAdd(&g_cursor[d], 1);
        g_csr[p] = s;
    }
}

// ---------------------------------------------------------------------------
// GEMM1: hs1 = dinv * (x @ W1).  M=100000, K=512, N=40.  (round-2 config,
// measured 107us). 64 threads/block, 128 rows. Thread: 8 rows x 10 cols.
// ---------------------------------------------------------------------------
constexpr int KT = 16;               // k per tile
constexpr int NT = CIN / KT;         // 32 tiles
constexpr int RT = 128;              // rows per block
constexpr int XROW = 32;             // padded floats per row in xs

__global__ __launch_bounds__(64) void k_gemm1(const float* __restrict__ x,
                                              const float* __restrict__ W1) {
    __shared__ __align__(16) float xs[2][RT * XROW];   // 2 x 16 KB
    __shared__ __align__(16) float ws[2][KT * CH];     // 2 x 2.5 KB

    const int tid = threadIdx.x;
    const int rp = tid >> 2;          // 0..15 : rows rp*8 .. rp*8+7
    const int ct = tid & 3;           // 0..3  : cols ct*10 .. ct*10+9
    const int row0 = blockIdx.x * RT;

    const uint32_t xs_b[2] = { smem_u32(&xs[0][0]), smem_u32(&xs[1][0]) };
    const uint32_t ws_b[2] = { smem_u32(&ws[0][0]), smem_u32(&ws[1][0]) };

    auto stage = [&](int t) {
        int kt = t * KT;
        int buf = t & 1;
#pragma unroll
        for (int i = 0; i < 8; i++) {
            int idx = tid + 64 * i;         // 0..511
            int r = idx >> 2;
            int q = idx & 3;
            int gr = row0 + r;
            const float* src = x + (size_t)gr * CIN + kt + q * 4;
            uint32_t dst = xs_b[buf] + (uint32_t)(r * XROW + 4 * ((q + (r >> 3)) & 7)) * 4u;
            cp_async16(dst, src, (gr < NN) ? 16 : 0);
        }
#pragma unroll
        for (int i = 0; i < 3; i++) {
            int idx = tid + 64 * i;
            if (idx < 160)
                cp_async16(ws_b[buf] + (uint32_t)idx * 16u, W1 + kt * CH + idx * 4, 16);
        }
    };

    unsigned long long acc[8][5];
#pragma unroll
    for (int r = 0; r < 8; r++)
#pragma unroll
        for (int j = 0; j < 5; j++) acc[r][j] = 0ull;

    stage(0);
    cp_commit();

    for (int t = 0; t < NT; t++) {
        int buf = t & 1;
        if (t + 1 < NT) {
            stage(t + 1);
            cp_commit();
            cp_wait<1>();
        } else {
            cp_wait<0>();
        }
        __syncthreads();

        const float* xsb = &xs[buf][0];
        const float* wsb = &ws[buf][0];
#pragma unroll
        for (int k = 0; k < KT; k++) {
            unsigned long long wv[5];
            const float* wk = wsb + k * CH + ct * 10;
#pragma unroll
            for (int j = 0; j < 5; j++)
                wv[j] = *(const unsigned long long*)(wk + 2 * j);
            int pos = 4 * (((k >> 2) + rp) & 7) + (k & 3);
#pragma unroll
            for (int r = 0; r < 8; r++) {
                float xv = xsb[(rp * 8 + r) * XROW + pos];
                unsigned long long xd;
                asm("mov.b64 %0, {%1, %1};" : "=l"(xd) : "f"(xv));
#pragma unroll
                for (int j = 0; j < 5; j++)
                    acc[r][j] = ffma2(xd, wv[j], acc[r][j]);
            }
        }
        __syncthreads();
    }

    // epilogue: scale by dinv, write message buffer only (pull agg inits from it)
#pragma unroll
    for (int r = 0; r < 8; r++) {
        int gr = row0 + rp * 8 + r;
        if (gr < NN) {
            float dv = g_dinv[gr];
#pragma unroll
            for (int j = 0; j < 5; j++) {
                unsigned long long a = acc[r][j];
                float lo = __uint_as_float((unsigned)a) * dv;
                float hi = __uint_as_float((unsigned)(a >> 32)) * dv;
                int c = ct * 10 + 2 * j;
                *(float2*)&g_h1[(size_t)gr * CH + c] = make_float2(lo, hi);
            }
        }
    }
}

// ---------------------------------------------------------------------------
// Aggregation layer 1 (PULL): 10 threads per node, each owns one float4
// slice of the 40 channels. acc init = own hs (self loop), then gather
// neighbors via CSR. Single write to g_acc1.
// ---------------------------------------------------------------------------
__global__ void k_agg1() {
    unsigned t = blockIdx.x * 256u + threadIdx.x;
    unsigned node = t / 10u;
    if (node >= (unsigned)NN) return;
    unsigned q = t - node * 10u;
    const float4* base = (const float4*)g_h1;

    float4 acc = base[(size_t)node * 10 + q];   // self term (hs[node])
    int beg = g_rowstart[node];
    int len = g_deg[node];

    int i = 0;
    for (; i + 2 <= len; i += 2) {
        int s0 = __ldg(&g_csr[beg + i]);
        int s1 = __ldg(&g_csr[beg + i + 1]);
        float4 v0 = base[(size_t)s0 * 10 + q];
        float4 v1 = base[(size_t)s1 * 10 + q];
        acc.x += v0.x + v1.x;
        acc.y += v0.y + v1.y;
        acc.z += v0.z + v1.z;
        acc.w += v0.w + v1.w;
    }
    if (i < len) {
        int s0 = __ldg(&g_csr[beg + i]);
        float4 v0 = base[(size_t)s0 * 10 + q];
        acc.x += v0.x; acc.y += v0.y; acc.z += v0.z; acc.w += v0.w;
    }
    ((float4*)g_acc1)[(size_t)node * 10 + q] = acc;
}

// ---------------------------------------------------------------------------
// Layer-1 finish + GEMM2: r = relu(dinv*acc1 + b1); hs2 = dinv * (r @ W2)
// ---------------------------------------------------------------------------
__global__ __launch_bounds__(128) void k_layer2(const float* __restrict__ W2,
                                                const float* __restrict__ b1) {
    __shared__ float w2s[CH * COUT];
    __shared__ float b1s[CH];
    int tid = threadIdx.x;
    for (int i = tid; i < CH * COUT; i += 128) w2s[i] = W2[i];
    if (tid < CH) b1s[tid] = b1[tid];
    __syncthreads();

    int r = blockIdx.x * 128 + tid;
    if (r >= NN) return;
    float dv = g_dinv[r];

    float rv[CH];
#pragma unroll
    for (int q = 0; q < 10; q++) {
        float4 v = *(const float4*)&g_acc1[(size_t)r * CH + q * 4];
        rv[4 * q + 0] = fmaxf(dv * v.x + b1s[4 * q + 0], 0.f);
        rv[4 * q + 1] = fmaxf(dv * v.y + b1s[4 * q + 1], 0.f);
        rv[4 * q + 2] = fmaxf(dv * v.z + b1s[4 * q + 2], 0.f);
        rv[4 * q + 3] = fmaxf(dv * v.w + b1s[4 * q + 3], 0.f);
    }

    float acc[COUT];
#pragma unroll
    for (int c = 0; c < COUT; c++) acc[c] = 0.f;
#pragma unroll
    for (int k = 0; k < CH; k++) {
        float xv = rv[k];
#pragma unroll
        for (int c = 0; c < COUT; c++)
            acc[c] = fmaf(xv, w2s[k * COUT + c], acc[c]);
    }

#pragma unroll
    for (int q = 0; q < 5; q++) {
        float4 o = make_float4(dv * acc[4 * q + 0], dv * acc[4 * q + 1],
                               dv * acc[4 * q + 2], dv * acc[4 * q + 3]);
        *(float4*)&g_h2[(size_t)r * COUT + 4 * q] = o;
    }
}

// ---------------------------------------------------------------------------
// Aggregation layer 2 (PULL) fused with final epilogue:
// 5 threads per node. out = dinv * (self + sum neighbors) + b2
// ---------------------------------------------------------------------------
__global__ void k_agg2(float* __restrict__ out, const float* __restrict__ b2) {
    unsigned t = blockIdx.x * 256u + threadIdx.x;
    unsigned node = t / 5u;
    if (node >= (unsigned)NN) return;
    unsigned q = t - node * 5u;
    const float4* base = (const float4*)g_h2;

    float4 acc = base[(size_t)node * 5 + q];    // self term
    int beg = g_rowstart[node];
    int len = g_deg[node];

    int i = 0;
    for (; i + 2 <= len; i += 2) {
        int s0 = __ldg(&g_csr[beg + i]);
        int s1 = __ldg(&g_csr[beg + i + 1]);
        float4 v0 = base[(size_t)s0 * 5 + q];
        float4 v1 = base[(size_t)s1 * 5 + q];
        acc.x += v0.x + v1.x;
        acc.y += v0.y + v1.y;
        acc.z += v0.z + v1.z;
        acc.w += v0.w + v1.w;
    }
    if (i < len) {
        int s0 = __ldg(&g_csr[beg + i]);
        float4 v0 = base[(size_t)s0 * 5 + q];
        acc.x += v0.x; acc.y += v0.y; acc.z += v0.z; acc.w += v0.w;
    }

    float dv = g_dinv[node];
    float4 b = *(const float4*)&b2[q * 4];
    float4 o = make_float4(dv * acc.x + b.x, dv * acc.y + b.y,
                           dv * acc.z + b.z, dv * acc.w + b.w);
    ((float4*)out)[(size_t)node * 5 + q] = o;
}

// ---------------------------------------------------------------------------
extern "C" void kernel_launch(void* const* d_in, const int* in_sizes, int n_in,
                              void* d_out, int out_size) {
    const float* x  = (const float*)d_in[0];
    const int*   ei = (const int*)d_in[1];
    const float* W1 = (const float*)d_in[2];
    const float* b1 = (const float*)d_in[3];
    const float* W2 = (const float*)d_in[4];
    const float* b2 = (const float*)d_in[5];
    float* out = (float*)d_out;

    k_deg_init<<<(NN + 255) / 256, 256>>>();
    k_deg_count<<<(NE + 255) / 256, 256>>>(ei);
    k_dinv<<<(NN + 255) / 256, 256>>>();
    k_scan1<<<SCAN_NB, SCAN_B>>>();
    k_scan2<<<1, 128>>>();
    k_scan3<<<SCAN_NB, SCAN_B>>>();
    k_fill<<<(NE + 255) / 256, 256>>>(ei);
    k_gemm1<<<(NN + RT - 1) / RT, 64>>>(x, W1);
    {
        long long th = (long long)NN * 10;
        k_agg1<<<(unsigned)((th + 255) / 256), 256>>>();
    }
    k_layer2<<<(NN + 127) / 128, 128>>>(W2, b1);
    {
        long long th = (long long)NN * 5;
        k_agg2<<<(unsigned)((th + 255) / 256), 256>>>(out, b2);
    }
}

// round 13
// speedup vs baseline: 1.7273x; 1.1180x over previous
#include <cuda_runtime.h>
#include <cuda_fp16.h>
#include <cstdint>

constexpr int NN = 100000;    // nodes
constexpr int NE = 3200000;   // edges
constexpr int CIN = 512;
constexpr int CH  = 40;
constexpr int COUT = 20;

constexpr int SCAN_B  = 1024;
constexpr int SCAN_NB = (NN + SCAN_B - 1) / SCAN_B;   // 98

// Scratch (__device__ globals: allocation-free per harness rules)
__device__ __align__(16) __half g_h1[(size_t)NN * CH];    // fp16 messages L1
__device__ __align__(16) float  g_acc1[(size_t)NN * CH];  // fp32 accumulator
__device__ __align__(16) __half g_h2[(size_t)NN * COUT];  // fp16 messages L2
__device__ float g_dinv[NN];
__device__ int   g_deg[NN];       // in-degree WITHOUT self loop
__device__ int   g_rowstart[NN];
__device__ int   g_cursor[NN];
__device__ int   g_csr[NE];       // src ids grouped by dst
__device__ int   g_scan[NN];
__device__ int   g_bsum[SCAN_NB];

// ---------------------------------------------------------------------------
// helpers
// ---------------------------------------------------------------------------
__device__ __forceinline__ unsigned long long ffma2(unsigned long long a,
                                                    unsigned long long b,
                                                    unsigned long long c) {
    unsigned long long d;
    asm("fma.rn.f32x2 %0, %1, %2, %3;" : "=l"(d) : "l"(a), "l"(b), "l"(c));
    return d;
}

__device__ __forceinline__ void cp_async16(uint32_t dst_smem, const void* src,
                                           int src_bytes) {
    asm volatile("cp.async.cg.shared.global [%0], [%1], 16, %2;"
                 :: "r"(dst_smem), "l"(src), "r"(src_bytes));
}
__device__ __forceinline__ void cp_commit() {
    asm volatile("cp.async.commit_group;");
}
template <int N>
__device__ __forceinline__ void cp_wait() {
    asm volatile("cp.async.wait_group %0;" :: "n"(N));
}

__device__ __forceinline__ uint32_t smem_u32(const void* p) {
    uint32_t a;
    asm("{ .reg .u64 t; cvta.to.shared.u64 t, %1; cvt.u32.u64 %0, t; }"
        : "=r"(a) : "l"(p));
    return a;
}

// add 4 fp16 pairs (uint4) into 8 fp32 accumulators
__device__ __forceinline__ void acc8_h(const uint4 v, float* a) {
    float2 f0 = __half22float2(*(const __half2*)&v.x);
    float2 f1 = __half22float2(*(const __half2*)&v.y);
    float2 f2 = __half22float2(*(const __half2*)&v.z);
    float2 f3 = __half22float2(*(const __half2*)&v.w);
    a[0] += f0.x; a[1] += f0.y; a[2] += f1.x; a[3] += f1.y;
    a[4] += f2.x; a[5] += f2.y; a[6] += f3.x; a[7] += f3.y;
}

__device__ __forceinline__ void acc4_h(const uint2 v, float* a) {
    float2 f0 = __half22float2(*(const __half2*)&v.x);
    float2 f1 = __half22float2(*(const __half2*)&v.y);
    a[0] += f0.x; a[1] += f0.y; a[2] += f1.x; a[3] += f1.y;
}

// ---------------------------------------------------------------------------
// degree / dinv / CSR build
// ---------------------------------------------------------------------------
__global__ void k_deg_init() {
    int i = blockIdx.x * 256 + threadIdx.x;
    if (i < NN) g_deg[i] = 0;
}
__global__ void k_deg_count(const int* __restrict__ ei) {
    int e = blockIdx.x * 256 + threadIdx.x;
    if (e < NE) atomicAdd(&g_deg[ei[NE + e]], 1);
}
__global__ void k_dinv() {
    int i = blockIdx.x * 256 + threadIdx.x;
    if (i < NN) g_dinv[i] = rsqrtf((float)(g_deg[i] + 1));  // +1 self loop
}

// --- parallel scan, phase 1: per-block inclusive scan + block totals -------
__global__ __launch_bounds__(SCAN_B) void k_scan1() {
    const int t = threadIdx.x, b = blockIdx.x;
    const int i = b * SCAN_B + t;
    int v = (i < NN) ? g_deg[i] : 0;
    const int lane = t & 31, warp = t >> 5;
    int s = v;
#pragma unroll
    for (int o = 1; o < 32; o <<= 1) {
        int u = __shfl_up_sync(~0u, s, o);
        if (lane >= o) s += u;
    }
    __shared__ int wsum[32];
    if (lane == 31) wsum[warp] = s;
    __syncthreads();
    if (warp == 0) {
        int ws = wsum[lane];
#pragma unroll
        for (int o = 1; o < 32; o <<= 1) {
            int u = __shfl_up_sync(~0u, ws, o);
            if (lane >= o) ws += u;
        }
        wsum[lane] = ws;
    }
    __syncthreads();
    int incl = s + (warp ? wsum[warp - 1] : 0);
    if (i < NN) g_scan[i] = incl;
    if (t == SCAN_B - 1) g_bsum[b] = incl;
}

// --- phase 2: exclusive scan of the 98 block totals ------------------------
__global__ __launch_bounds__(128) void k_scan2() {
    const int t = threadIdx.x;
    int v = (t < SCAN_NB) ? g_bsum[t] : 0;
    const int lane = t & 31, warp = t >> 5;
    int s = v;
#pragma unroll
    for (int o = 1; o < 32; o <<= 1) {
        int u = __shfl_up_sync(~0u, s, o);
        if (lane >= o) s += u;
    }
    __shared__ int wsum[4];
    if (lane == 31) wsum[warp] = s;
    __syncthreads();
    int add = 0;
    for (int w = 0; w < warp; w++) add += wsum[w];
    int incl = s + add;
    if (t < SCAN_NB) g_bsum[t] = incl - v;   // exclusive block offset
}

// --- phase 3: rowstart / cursor --------------------------------------------
__global__ __launch_bounds__(SCAN_B) void k_scan3() {
    const int t = threadIdx.x, b = blockIdx.x;
    const int i = b * SCAN_B + t;
    if (i < NN) {
        int rs = g_bsum[b] + g_scan[i] - g_deg[i];
        g_rowstart[i] = rs;
        g_cursor[i] = rs;
    }
}

__global__ void k_fill(const int* __restrict__ ei) {
    int e = blockIdx.x * 256 + threadIdx.x;
    if (e < NE) {
        int s = ei[e];
        int d = ei[NE + e];
        int p = atomicAdd(&g_cursor[d], 1);
        g_csr[p] = s;
    }
}

// ---------------------------------------------------------------------------
// GEMM1: hs1 = dinv * (x @ W1) -> fp16.  (measured-best round-2 config)
// ---------------------------------------------------------------------------
constexpr int KT = 16;
constexpr int NT = CIN / KT;
constexpr int RT = 128;
constexpr int XROW = 32;

__global__ __launch_bounds__(64) void k_gemm1(const float* __restrict__ x,
                                              const float* __restrict__ W1) {
    __shared__ __align__(16) float xs[2][RT * XROW];
    __shared__ __align__(16) float ws[2][KT * CH];

    const int tid = threadIdx.x;
    const int rp = tid >> 2;
    const int ct = tid & 3;
    const int row0 = blockIdx.x * RT;

    const uint32_t xs_b[2] = { smem_u32(&xs[0][0]), smem_u32(&xs[1][0]) };
    const uint32_t ws_b[2] = { smem_u32(&ws[0][0]), smem_u32(&ws[1][0]) };

    auto stage = [&](int t) {
        int kt = t * KT;
        int buf = t & 1;
#pragma unroll
        for (int i = 0; i < 8; i++) {
            int idx = tid + 64 * i;
            int r = idx >> 2;
            int q = idx & 3;
            int gr = row0 + r;
            const float* src = x + (size_t)gr * CIN + kt + q * 4;
            uint32_t dst = xs_b[buf] + (uint32_t)(r * XROW + 4 * ((q + (r >> 3)) & 7)) * 4u;
            cp_async16(dst, src, (gr < NN) ? 16 : 0);
        }
#pragma unroll
        for (int i = 0; i < 3; i++) {
            int idx = tid + 64 * i;
            if (idx < 160)
                cp_async16(ws_b[buf] + (uint32_t)idx * 16u, W1 + kt * CH + idx * 4, 16);
        }
    };

    unsigned long long acc[8][5];
#pragma unroll
    for (int r = 0; r < 8; r++)
#pragma unroll
        for (int j = 0; j < 5; j++) acc[r][j] = 0ull;

    stage(0);
    cp_commit();

    for (int t = 0; t < NT; t++) {
        int buf = t & 1;
        if (t + 1 < NT) {
            stage(t + 1);
            cp_commit();
            cp_wait<1>();
        } else {
            cp_wait<0>();
        }
        __syncthreads();

        const float* xsb = &xs[buf][0];
        const float* wsb = &ws[buf][0];
#pragma unroll
        for (int k = 0; k < KT; k++) {
            unsigned long long wv[5];
            const float* wk = wsb + k * CH + ct * 10;
#pragma unroll
            for (int j = 0; j < 5; j++)
                wv[j] = *(const unsigned long long*)(wk + 2 * j);
            int pos = 4 * (((k >> 2) + rp) & 7) + (k & 3);
#pragma unroll
            for (int r = 0; r < 8; r++) {
                float xv = xsb[(rp * 8 + r) * XROW + pos];
                unsigned long long xd;
                asm("mov.b64 %0, {%1, %1};" : "=l"(xd) : "f"(xv));
#pragma unroll
                for (int j = 0; j < 5; j++)
                    acc[r][j] = ffma2(xd, wv[j], acc[r][j]);
            }
        }
        __syncthreads();
    }

    // epilogue: scale by dinv, quantize to fp16 message buffer
#pragma unroll
    for (int r = 0; r < 8; r++) {
        int gr = row0 + rp * 8 + r;
        if (gr < NN) {
            float dv = g_dinv[gr];
#pragma unroll
            for (int j = 0; j < 5; j++) {
                unsigned long long a = acc[r][j];
                float lo = __uint_as_float((unsigned)a) * dv;
                float hi = __uint_as_float((unsigned)(a >> 32)) * dv;
                int c = ct * 10 + 2 * j;
                *(__half2*)&g_h1[(size_t)gr * CH + c] = __floats2half2_rn(lo, hi);
            }
        }
    }
}

// ---------------------------------------------------------------------------
// Aggregation layer 1 (PULL, fp16 msgs): 5 threads/node, each owns 8 channels
// (one uint4 = 4 half2). Accumulate fp32, single fp32 write to g_acc1.
// ---------------------------------------------------------------------------
__global__ void k_agg1() {
    unsigned t = blockIdx.x * 256u + threadIdx.x;
    unsigned node = t / 5u;
    if (node >= (unsigned)NN) return;
    unsigned q = t - node * 5u;
    const uint4* base = (const uint4*)g_h1;   // node stride = 5 uint4

    float a[8];
#pragma unroll
    for (int i = 0; i < 8; i++) a[i] = 0.f;
    acc8_h(base[(size_t)node * 5 + q], a);    // self term

    int beg = g_rowstart[node];
    int len = g_deg[node];
    int i = 0;
    for (; i + 2 <= len; i += 2) {
        int s0 = __ldg(&g_csr[beg + i]);
        int s1 = __ldg(&g_csr[beg + i + 1]);
        uint4 v0 = base[(size_t)s0 * 5 + q];
        uint4 v1 = base[(size_t)s1 * 5 + q];
        acc8_h(v0, a);
        acc8_h(v1, a);
    }
    if (i < len) {
        int s0 = __ldg(&g_csr[beg + i]);
        acc8_h(base[(size_t)s0 * 5 + q], a);
    }

    float4* dst = (float4*)&g_acc1[(size_t)node * CH + q * 8];
    dst[0] = make_float4(a[0], a[1], a[2], a[3]);
    dst[1] = make_float4(a[4], a[5], a[6], a[7]);
}

// ---------------------------------------------------------------------------
// Layer-1 finish + GEMM2: r = relu(dinv*acc1 + b1); hs2 = dinv*(r @ W2) -> fp16
// ---------------------------------------------------------------------------
__global__ __launch_bounds__(128) void k_layer2(const float* __restrict__ W2,
                                                const float* __restrict__ b1) {
    __shared__ float w2s[CH * COUT];
    __shared__ float b1s[CH];
    int tid = threadIdx.x;
    for (int i = tid; i < CH * COUT; i += 128) w2s[i] = W2[i];
    if (tid < CH) b1s[tid] = b1[tid];
    __syncthreads();

    int r = blockIdx.x * 128 + tid;
    if (r >= NN) return;
    float dv = g_dinv[r];

    float rv[CH];
#pragma unroll
    for (int q = 0; q < 10; q++) {
        float4 v = *(const float4*)&g_acc1[(size_t)r * CH + q * 4];
        rv[4 * q + 0] = fmaxf(dv * v.x + b1s[4 * q + 0], 0.f);
        rv[4 * q + 1] = fmaxf(dv * v.y + b1s[4 * q + 1], 0.f);
        rv[4 * q + 2] = fmaxf(dv * v.z + b1s[4 * q + 2], 0.f);
        rv[4 * q + 3] = fmaxf(dv * v.w + b1s[4 * q + 3], 0.f);
    }

    float acc[COUT];
#pragma unroll
    for (int c = 0; c < COUT; c++) acc[c] = 0.f;
#pragma unroll
    for (int k = 0; k < CH; k++) {
        float xv = rv[k];
#pragma unroll
        for (int c = 0; c < COUT; c++)
            acc[c] = fmaf(xv, w2s[k * COUT + c], acc[c]);
    }

#pragma unroll
    for (int p = 0; p < 10; p++) {
        __half2 h = __floats2half2_rn(dv * acc[2 * p], dv * acc[2 * p + 1]);
        *(__half2*)&g_h2[(size_t)r * COUT + 2 * p] = h;
    }
}

// ---------------------------------------------------------------------------
// Aggregation layer 2 (PULL, fp16 msgs) fused with final epilogue:
// 5 threads/node, each owns 4 channels (uint2 = 2 half2).
// out = dinv * (self + sum neighbors) + b2
// ---------------------------------------------------------------------------
__global__ void k_agg2(float* __restrict__ out, const float* __restrict__ b2) {
    unsigned t = blockIdx.x * 256u + threadIdx.x;
    unsigned node = t / 5u;
    if (node >= (unsigned)NN) return;
    unsigned q = t - node * 5u;
    const uint2* base = (const uint2*)g_h2;   // node stride = 5 uint2

    float a[4];
#pragma unroll
    for (int i = 0; i < 4; i++) a[i] = 0.f;
    acc4_h(base[(size_t)node * 5 + q], a);    // self term

    int beg = g_rowstart[node];
    int len = g_deg[node];
    int i = 0;
    for (; i + 2 <= len; i += 2) {
        int s0 = __ldg(&g_csr[beg + i]);
        int s1 = __ldg(&g_csr[beg + i + 1]);
        uint2 v0 = base[(size_t)s0 * 5 + q];
        uint2 v1 = base[(size_t)s1 * 5 + q];
        acc4_h(v0, a);
        acc4_h(v1, a);
    }
    if (i < len) {
        int s0 = __ldg(&g_csr[beg + i]);
        acc4_h(base[(size_t)s0 * 5 + q], a);
    }

    float dv = g_dinv[node];
    float4 b = *(const float4*)&b2[q * 4];
    float4 o = make_float4(dv * a[0] + b.x, dv * a[1] + b.y,
                           dv * a[2] + b.z, dv * a[3] + b.w);
    ((float4*)out)[(size_t)node * 5 + q] = o;
}

// ---------------------------------------------------------------------------
extern "C" void kernel_launch(void* const* d_in, const int* in_sizes, int n_in,
                              void* d_out, int out_size) {
    const float* x  = (const float*)d_in[0];
    const int*   ei = (const int*)d_in[1];
    const float* W1 = (const float*)d_in[2];
    const float* b1 = (const float*)d_in[3];
    const float* W2 = (const float*)d_in[4];
    const float* b2 = (const float*)d_in[5];
    float* out = (float*)d_out;

    k_deg_init<<<(NN + 255) / 256, 256>>>();
    k_deg_count<<<(NE + 255) / 256, 256>>>(ei);
    k_dinv<<<(NN + 255) / 256, 256>>>();
    k_scan1<<<SCAN_NB, SCAN_B>>>();
    k_scan2<<<1, 128>>>();
    k_scan3<<<SCAN_NB, SCAN_B>>>();
    k_fill<<<(NE + 255) / 256, 256>>>(ei);
    k_gemm1<<<(NN + RT - 1) / RT, 64>>>(x, W1);
    {
        long long th = (long long)NN * 5;
        k_agg1<<<(unsigned)((th + 255) / 256), 256>>>();
    }
    k_layer2<<<(NN + 127) / 128, 128>>>(W2, b1);
    {
        long long th = (long long)NN * 5;
        k_agg2<<<(unsigned)((th + 255) / 256), 256>>>(out, b2);
    }
}